// round 3
// baseline (speedup 1.0000x reference)
#include <cuda_runtime.h>

#define BB 8
#define CC 128
#define KK 19
#define NPIX 65536
#define BN (BB*NPIX)

// ---------------- scratch (device globals; no allocation) ----------------
__device__ float         g_e[BN];          // pass1: per-pixel max logit; pass2: exp weight
__device__ unsigned char g_cls[BN];        // per-pixel argmax class
__device__ unsigned      g_mxEnc[BB*KK];   // per-(b,k) max, order-preserving uint encoding
__device__ float         g_Z[BB*KK];       // per-(b,k) sum of exp
__device__ float         g_cnt[BB*KK];     // per-(b,k) pixel count
__device__ float         g_Xs[BB*KK*CC];   // unweighted segment sums of x
__device__ float         g_Xw[BB*KK*CC];   // exp-weighted segment sums of x
__device__ float         g_gmat[BB*KK*CC]; // g[b][k][d]
__device__ float         g_S1[BB*CC*KK];   // S1[b][d][k]

// order-preserving float<->uint for atomicMax
__device__ __forceinline__ unsigned fenc(float f){
    unsigned u = __float_as_uint(f);
    return (u & 0x80000000u) ? ~u : (u | 0x80000000u);
}
__device__ __forceinline__ float fdec(unsigned e){
    unsigned u = (e & 0x80000000u) ? (e & 0x7fffffffu) : ~e;
    return __uint_as_float(u);
}

// ---------------- pass 0: zero accumulators ----------------
__global__ void k_init(){
    int i = blockIdx.x*blockDim.x + threadIdx.x;
    int stride = gridDim.x*blockDim.x;
    if (i < BB*KK){ g_mxEnc[i]=0u; g_Z[i]=0.f; g_cnt[i]=0.f; }
    for (int j=i; j<BB*KK*CC; j+=stride){ g_Xs[j]=0.f; g_Xw[j]=0.f; }
}

// ---------------- pass 1: per-pixel argmax + per-class max ----------------
__global__ void k_argmax(const float* __restrict__ preds){
    int b = blockIdx.y;
    int n = blockIdx.x*256 + threadIdx.x;
    const float* p = preds + (size_t)b*KK*NPIX + n;
    float best = p[0]; int bk = 0;
    #pragma unroll
    for (int k=1;k<KK;k++){
        float v = p[(size_t)k*NPIX];
        if (v > best){ best = v; bk = k; }   // strict >: first max, matches jnp.argmax
    }
    g_cls[b*NPIX+n] = (unsigned char)bk;
    g_e[b*NPIX+n]   = best;                  // stash max logit
    __shared__ unsigned sMax[KK];
    if (threadIdx.x < KK) sMax[threadIdx.x] = 0u;
    __syncthreads();
    atomicMax(&sMax[bk], fenc(best));
    __syncthreads();
    if (threadIdx.x < KK) atomicMax(&g_mxEnc[b*KK+threadIdx.x], sMax[threadIdx.x]);
}

// ---------------- pass 2: e = exp(p - mx), Z, cnt ----------------
__global__ void k_weights(){
    int b = blockIdx.y;
    int n = blockIdx.x*256 + threadIdx.x;
    int k = g_cls[b*NPIX+n];
    float pm = g_e[b*NPIX+n];
    float mx = fdec(g_mxEnc[b*KK+k]);
    float e = expf(pm - mx);
    g_e[b*NPIX+n] = e;
    __shared__ float sZ[KK], sC[KK];
    if (threadIdx.x < KK){ sZ[threadIdx.x]=0.f; sC[threadIdx.x]=0.f; }
    __syncthreads();
    atomicAdd(&sZ[k], e);
    atomicAdd(&sC[k], 1.0f);
    __syncthreads();
    if (threadIdx.x < KK){
        atomicAdd(&g_Z[b*KK+threadIdx.x],   sZ[threadIdx.x]);
        atomicAdd(&g_cnt[b*KK+threadIdx.x], sC[threadIdx.x]);
    }
}

// ---------------- pass 3: heavy segment sums over x ----------------
// Block: 256 threads (8 warps). lane = channel within 32-channel chunk.
// Block covers 1024 pixels x 32 channels, as 8 pixel-chunks of 128, x staged
// through smem via cp.async double buffer. Per pixel-step the class is
// warp-uniform -> 19-case switch updates register accumulators.
#define PTILE 1024
#define PCH   128          // pixels per chunk
#define NCHUNK (PTILE/PCH) // 8
#define XSTRIDE 130        // floats per smem row (520B, 8B aligned, 2-way conflict max)

__device__ __forceinline__ void cpasync8(unsigned saddr, const void* gaddr){
    asm volatile("cp.async.ca.shared.global [%0], [%1], 8;" :: "r"(saddr), "l"(gaddr));
}
__device__ __forceinline__ void cpasync4(unsigned saddr, const void* gaddr){
    asm volatile("cp.async.ca.shared.global [%0], [%1], 4;" :: "r"(saddr), "l"(gaddr));
}
__device__ __forceinline__ void cpcommit(){ asm volatile("cp.async.commit_group;"); }
template<int N> __device__ __forceinline__ void cpwait(){ asm volatile("cp.async.wait_group %0;" :: "n"(N)); }

__global__ void __launch_bounds__(256, 3) k_segsum(const float* __restrict__ x){
    __shared__ float         sX[2][32*XSTRIDE];   // 33.3 KB
    __shared__ float         sE[2][PCH];          // 1 KB
    __shared__ unsigned char sCls[2][PCH];        // 256 B

    const int b    = blockIdx.z;
    const int c0   = blockIdx.y*32;
    const int pix0 = blockIdx.x*PTILE;
    const int t    = threadIdx.x;
    const int warp = t >> 5;
    const int lane = t & 31;

    const float* xb = x + (size_t)b*CC*NPIX + (size_t)c0*NPIX + pix0;

    unsigned sxb = (unsigned)__cvta_generic_to_shared(&sX[0][0]);
    unsigned seb = (unsigned)__cvta_generic_to_shared(&sE[0][0]);
    unsigned scb = (unsigned)__cvta_generic_to_shared(&sCls[0][0]);

    // prefetch chunk `ch` into buffer buf
    auto prefetch = [&](int ch, int buf){
        const float* gsrc = xb + ch*PCH;
        unsigned sx = sxb + (unsigned)buf*(32*XSTRIDE*4);
        // 32 rows x 64 8B-units = 2048 ops / 256 threads = 8 per thread
        #pragma unroll
        for (int j=0;j<8;j++){
            int u    = t + j*256;
            int row  = u >> 6;
            int unit = u & 63;
            cpasync8(sx + (unsigned)(row*XSTRIDE + unit*2)*4,
                     gsrc + (size_t)row*NPIX + unit*2);
        }
        if (t < 64){   // e: 128 floats = 64 8B units
            cpasync8(seb + (unsigned)buf*(PCH*4) + (unsigned)t*8,
                     g_e + (size_t)b*NPIX + pix0 + ch*PCH + t*2);
        } else if (t < 96){ // cls: 128 bytes = 32 4B units
            int u = t - 64;
            cpasync4(scb + (unsigned)buf*PCH + (unsigned)u*4,
                     g_cls + (size_t)b*NPIX + pix0 + ch*PCH + u*4);
        }
        cpcommit();
    };

    float accS[KK], accW[KK];
    #pragma unroll
    for (int k=0;k<KK;k++){ accS[k]=0.f; accW[k]=0.f; }

    prefetch(0, 0);
    for (int ch=0; ch<NCHUNK; ++ch){
        int buf = ch & 1;
        if (ch+1 < NCHUNK) prefetch(ch+1, buf^1);
        if (ch+1 < NCHUNK) cpwait<1>(); else cpwait<0>();
        __syncthreads();

        // this warp handles 16 pixels of the 128-pixel chunk
        const int wp0 = warp*16;
        const float* xrow = &sX[buf][lane*XSTRIDE];
        #pragma unroll 4
        for (int i=0;i<16;i++){
            int p = wp0 + i;
            float e = sE[buf][p];            // warp-uniform (broadcast)
            int   k = sCls[buf][p];          // warp-uniform
            float v = xrow[p];
            float ve = v*e;
            switch(k){
            case 0:  accS[0] +=v; accW[0] +=ve; break;
            case 1:  accS[1] +=v; accW[1] +=ve; break;
            case 2:  accS[2] +=v; accW[2] +=ve; break;
            case 3:  accS[3] +=v; accW[3] +=ve; break;
            case 4:  accS[4] +=v; accW[4] +=ve; break;
            case 5:  accS[5] +=v; accW[5] +=ve; break;
            case 6:  accS[6] +=v; accW[6] +=ve; break;
            case 7:  accS[7] +=v; accW[7] +=ve; break;
            case 8:  accS[8] +=v; accW[8] +=ve; break;
            case 9:  accS[9] +=v; accW[9] +=ve; break;
            case 10: accS[10]+=v; accW[10]+=ve; break;
            case 11: accS[11]+=v; accW[11]+=ve; break;
            case 12: accS[12]+=v; accW[12]+=ve; break;
            case 13: accS[13]+=v; accW[13]+=ve; break;
            case 14: accS[14]+=v; accW[14]+=ve; break;
            case 15: accS[15]+=v; accW[15]+=ve; break;
            case 16: accS[16]+=v; accW[16]+=ve; break;
            case 17: accS[17]+=v; accW[17]+=ve; break;
            default: accS[18]+=v; accW[18]+=ve; break;
            }
        }
        __syncthreads();
    }

    // flush: lane owns channel c0+lane; 19 classes x 2 arrays
    #pragma unroll
    for (int k=0;k<KK;k++){
        atomicAdd(&g_Xs[(b*KK+k)*CC + c0 + lane], accS[k]);
        atomicAdd(&g_Xw[(b*KK+k)*CC + c0 + lane], accW[k]);
    }
}

// ---------------- pass 4: tiny GEMMs -> g[k][d], S1[d][k] ----------------
__global__ void k_smallmm(const float* __restrict__ w1, const float* __restrict__ b1,
                          const float* __restrict__ w2, const float* __restrict__ b2){
    int b = blockIdx.x, t = threadIdx.x;   // t = output channel d (128 threads)
    __shared__ float sXw[KK][CC], sXs[KK][CC], sZ[KK], sCnt[KK];
    for (int i=t; i<KK*CC; i+=CC){
        sXw[i/CC][i%CC] = g_Xw[b*KK*CC + i];
        sXs[i/CC][i%CC] = g_Xs[b*KK*CC + i];
    }
    if (t < KK){
        sZ[t]   = fmaxf(g_Z[b*KK+t], 1e-30f);
        sCnt[t] = g_cnt[b*KK+t];
    }
    __syncthreads();
    float ga[KK], sa[KK];
    #pragma unroll
    for (int k=0;k<KK;k++){ ga[k]=0.f; sa[k]=0.f; }
    for (int c=0;c<CC;c++){
        float w2v = w2[t*CC + c];
        float w1v = w1[t*CC + c];
        #pragma unroll
        for (int k=0;k<KK;k++){
            ga[k] = fmaf(sXw[k][c], w2v, ga[k]);
            sa[k] = fmaf(sXs[k][c], w1v, sa[k]);
        }
    }
    #pragma unroll
    for (int k=0;k<KK;k++){
        g_gmat[(b*KK+k)*CC + t] = ga[k]/sZ[k] + b2[t];
        g_S1[(b*CC+t)*KK + k]   = sa[k] + b1[t]*sCnt[k];
    }
}

// ---------------- pass 5: gc = S1 @ g / sqrt(C), row softmax (128 threads!) ----
__global__ void k_out(float* __restrict__ out){
    int b = blockIdx.y, d1 = blockIdx.x, t = threadIdx.x;   // t in [0,128)
    __shared__ float s1[KK];
    __shared__ float redm[4], reds[4];
    if (t < KK) s1[t] = g_S1[(b*CC+d1)*KK + t];
    __syncthreads();
    float acc = 0.f;
    const float* gb = g_gmat + b*KK*CC + t;
    #pragma unroll
    for (int k=0;k<KK;k++) acc = fmaf(s1[k], gb[k*CC], acc);
    acc *= 0.08838834764831845f;   // 128^-0.5
    float m = acc;
    #pragma unroll
    for (int o=16;o;o>>=1) m = fmaxf(m, __shfl_xor_sync(0xffffffffu, m, o));
    if ((t&31)==0) redm[t>>5] = m;
    __syncthreads();
    m = fmaxf(fmaxf(redm[0],redm[1]), fmaxf(redm[2],redm[3]));
    float e = expf(acc - m);
    float s = e;
    #pragma unroll
    for (int o=16;o;o>>=1) s += __shfl_xor_sync(0xffffffffu, s, o);
    if ((t&31)==0) reds[t>>5] = s;
    __syncthreads();
    s = reds[0]+reds[1]+reds[2]+reds[3];
    out[((size_t)(b*CC+d1))*CC + t] = e/s;
}

// ---------------- launch ----------------
extern "C" void kernel_launch(void* const* d_in, const int* in_sizes, int n_in,
                              void* d_out, int out_size){
    const float* x     = (const float*)d_in[0];
    const float* preds = (const float*)d_in[1];
    const float* w1    = (const float*)d_in[2];
    const float* b1    = (const float*)d_in[3];
    const float* w2    = (const float*)d_in[4];
    const float* b2    = (const float*)d_in[5];
    float* out = (float*)d_out;

    k_init<<<80,256>>>();
    k_argmax <<<dim3(NPIX/256, BB), 256>>>(preds);
    k_weights<<<dim3(NPIX/256, BB), 256>>>();
    k_segsum <<<dim3(NPIX/PTILE, CC/32, BB), 256>>>(x);
    k_smallmm<<<BB, CC>>>(w1, b1, w2, b2);
    k_out    <<<dim3(CC, BB), CC>>>(out);
    (void)in_sizes; (void)n_in; (void)out_size;
}

// round 4
// speedup vs baseline: 1.2949x; 1.2949x over previous
#include <cuda_runtime.h>

#define BB 8
#define CC 128
#define KK 19
#define NPIX 65536
#define BN (BB*NPIX)

// ---------------- scratch (device globals; no allocation) ----------------
__device__ float         g_e[BN];          // pass1: per-pixel max logit
__device__ unsigned char g_cls[BN];        // per-pixel argmax class
__device__ float         g_eS[BN];         // class-sorted exp weights (per 128-seg)
__device__ unsigned short g_meta[BN];      // sorted: (perm_in_seg<<8) | cls
__device__ unsigned      g_mxEnc[BB*KK];   // per-(b,k) max, order-preserving enc
__device__ float         g_Z[BB*KK];       // per-(b,k) sum of exp
__device__ float         g_cnt[BB*KK];     // per-(b,k) pixel count
__device__ float         g_Xs[BB*KK*CC];   // unweighted segment sums of x
__device__ float         g_Xw[BB*KK*CC];   // exp-weighted segment sums of x
__device__ float         g_gmat[BB*KK*CC]; // g[b][k][d]
__device__ float         g_S1[BB*CC*KK];   // S1[b][d][k]

__device__ __forceinline__ unsigned fenc(float f){
    unsigned u = __float_as_uint(f);
    return (u & 0x80000000u) ? ~u : (u | 0x80000000u);
}
__device__ __forceinline__ float fdec(unsigned e){
    unsigned u = (e & 0x80000000u) ? (e & 0x7fffffffu) : ~e;
    return __uint_as_float(u);
}

// ---------------- pass 0: zero accumulators ----------------
__global__ void k_init(){
    int i = blockIdx.x*blockDim.x + threadIdx.x;
    int stride = gridDim.x*blockDim.x;
    if (i < BB*KK){ g_mxEnc[i]=0u; g_Z[i]=0.f; g_cnt[i]=0.f; }
    for (int j=i; j<BB*KK*CC; j+=stride){ g_Xs[j]=0.f; g_Xw[j]=0.f; }
}

// ---------------- pass 1: per-pixel argmax + per-class max ----------------
__global__ void k_argmax(const float* __restrict__ preds){
    int b = blockIdx.y;
    int n = blockIdx.x*256 + threadIdx.x;
    const float* p = preds + (size_t)b*KK*NPIX + n;
    float best = p[0]; int bk = 0;
    #pragma unroll
    for (int k=1;k<KK;k++){
        float v = p[(size_t)k*NPIX];
        if (v > best){ best = v; bk = k; }   // strict >: first max = jnp.argmax
    }
    g_cls[b*NPIX+n] = (unsigned char)bk;
    g_e[b*NPIX+n]   = best;
    __shared__ unsigned sMax[KK];
    if (threadIdx.x < KK) sMax[threadIdx.x] = 0u;
    __syncthreads();
    atomicMax(&sMax[bk], fenc(best));
    __syncthreads();
    if (threadIdx.x < KK) atomicMax(&g_mxEnc[b*KK+threadIdx.x], sMax[threadIdx.x]);
}

// ---------------- pass 2: e=exp(p-mx), Z, cnt, AND class-sort per 128-seg ----
__global__ void k_weights(){
    int b  = blockIdx.y;
    int n0 = blockIdx.x*256;
    int t  = threadIdx.x;
    int seg = t >> 7;          // 0/1 : which 128-pixel segment
    int i   = t & 127;         // pixel index within segment
    int n   = n0 + seg*128 + i;

    int   k  = g_cls[b*NPIX+n];
    float pm = g_e[b*NPIX+n];
    float mx = fdec(g_mxEnc[b*KK+k]);
    float e  = expf(pm - mx);

    __shared__ int   cnts[2][KK];
    __shared__ int   starts[2][KK];
    __shared__ float sZ[KK];
    if (t < 2*KK){ cnts[t/KK][t%KK] = 0; if (t < KK) sZ[t] = 0.f; }
    __syncthreads();
    int rank = atomicAdd(&cnts[seg][k], 1);
    atomicAdd(&sZ[k], e);
    __syncthreads();
    if (t < 2){
        int s = 0;
        #pragma unroll
        for (int kk=0;kk<KK;kk++){ starts[t][kk] = s; s += cnts[t][kk]; }
    }
    __syncthreads();
    int pos = starts[seg][k] + rank;
    int base = b*NPIX + n0 + seg*128;
    g_eS[base + pos]   = e;
    g_meta[base + pos] = (unsigned short)((i<<8) | k);
    if (t < KK){
        atomicAdd(&g_Z[b*KK+t],   sZ[t]);
        atomicAdd(&g_cnt[b*KK+t], (float)(cnts[0][t] + cnts[1][t]));
    }
}

// ---------------- pass 3: heavy segment sums over x ----------------
#define PTILE 1024
#define PCH   128
#define NCHUNK (PTILE/PCH)
#define XSTRIDE 130                      // 520 B/row: 8B aligned, 2-way conflict max
#define XWORDS (32*XSTRIDE)              // floats per buffer
#define OFF_E    (2*XWORDS*4)            // 33280
#define OFF_META (OFF_E + 2*PCH*4)       // 34304
#define SMEM_BYTES (OFF_META + 2*PCH*2)  // 34816

__device__ __forceinline__ void cpasync8(unsigned saddr, const void* gaddr){
    asm volatile("cp.async.ca.shared.global [%0], [%1], 8;" :: "r"(saddr), "l"(gaddr));
}
__device__ __forceinline__ void cpasync4(unsigned saddr, const void* gaddr){
    asm volatile("cp.async.ca.shared.global [%0], [%1], 4;" :: "r"(saddr), "l"(gaddr));
}
__device__ __forceinline__ void cpcommit(){ asm volatile("cp.async.commit_group;"); }
template<int N> __device__ __forceinline__ void cpwait(){ asm volatile("cp.async.wait_group %0;" :: "n"(N)); }

__global__ void __launch_bounds__(256, 4) k_segsum(const float* __restrict__ x){
    __shared__ __align__(16) unsigned char smemRaw[SMEM_BYTES];
    float*          sXf    = (float*)smemRaw;
    float*          sEf    = (float*)(smemRaw + OFF_E);
    unsigned short* sMetaA = (unsigned short*)(smemRaw + OFF_META);

    const int b    = blockIdx.z;
    const int c0   = blockIdx.y*32;
    const int pix0 = blockIdx.x*PTILE;
    const int t    = threadIdx.x;
    const int warp = t >> 5;
    const int lane = t & 31;

    const float* xb = x + (size_t)b*CC*NPIX + (size_t)c0*NPIX + pix0;

    unsigned sbase = (unsigned)__cvta_generic_to_shared(smemRaw);

    auto prefetch = [&](int ch, int buf){
        const float* gsrc = xb + ch*PCH;
        unsigned sx = sbase + (unsigned)buf*(XWORDS*4);
        #pragma unroll
        for (int j=0;j<8;j++){
            int u    = t + j*256;
            int row  = u >> 6;
            int unit = u & 63;
            cpasync8(sx + (unsigned)(row*XSTRIDE + unit*2)*4,
                     gsrc + (size_t)row*NPIX + unit*2);
        }
        if (t < 64){           // sorted e: 128 floats = 64 x 8B
            cpasync8(sbase + OFF_E + (unsigned)buf*(PCH*4) + (unsigned)t*8,
                     g_eS + (size_t)b*NPIX + pix0 + ch*PCH + t*2);
        } else if (t < 128){   // meta: 128 ushort = 64 x 4B
            int u = t - 64;
            cpasync4(sbase + OFF_META + (unsigned)buf*(PCH*2) + (unsigned)u*4,
                     g_meta + (size_t)b*NPIX + pix0 + ch*PCH + u*2);
        }
        cpcommit();
    };

    float accS[KK], accW[KK];
    #pragma unroll
    for (int k=0;k<KK;k++){ accS[k]=0.f; accW[k]=0.f; }

    prefetch(0, 0);
    for (int ch=0; ch<NCHUNK; ++ch){
        int buf = ch & 1;
        if (ch+1 < NCHUNK) prefetch(ch+1, buf^1);
        if (ch+1 < NCHUNK) cpwait<1>(); else cpwait<0>();
        __syncthreads();

        const float*          xrow = &sXf[buf*XWORDS + lane*XSTRIDE];
        const float*          eArr = &sEf[buf*PCH];
        const unsigned short* mArr = &sMetaA[buf*PCH];

        const int wp0  = warp*16;
        const int wend = wp0 + 16;
        int p = wp0;
        int meta = mArr[p];
        while (p < wend){
            int k = meta & 255;
            float ls = 0.f, lw = 0.f;
            bool cont = true;
            while (cont){
                float e = eArr[p];           // warp-uniform
                float v = xrow[meta >> 8];   // per-lane, uniform index
                ls += v;
                lw = fmaf(v, e, lw);
                ++p;
                if (p < wend){
                    meta = mArr[p];
                    cont = ((meta & 255) == k);
                } else cont = false;
            }
            switch(k){                       // once per run (~3-4 per chunk)
            case 0:  accS[0] +=ls; accW[0] +=lw; break;
            case 1:  accS[1] +=ls; accW[1] +=lw; break;
            case 2:  accS[2] +=ls; accW[2] +=lw; break;
            case 3:  accS[3] +=ls; accW[3] +=lw; break;
            case 4:  accS[4] +=ls; accW[4] +=lw; break;
            case 5:  accS[5] +=ls; accW[5] +=lw; break;
            case 6:  accS[6] +=ls; accW[6] +=lw; break;
            case 7:  accS[7] +=ls; accW[7] +=lw; break;
            case 8:  accS[8] +=ls; accW[8] +=lw; break;
            case 9:  accS[9] +=ls; accW[9] +=lw; break;
            case 10: accS[10]+=ls; accW[10]+=lw; break;
            case 11: accS[11]+=ls; accW[11]+=lw; break;
            case 12: accS[12]+=ls; accW[12]+=lw; break;
            case 13: accS[13]+=ls; accW[13]+=lw; break;
            case 14: accS[14]+=ls; accW[14]+=lw; break;
            case 15: accS[15]+=ls; accW[15]+=lw; break;
            case 16: accS[16]+=ls; accW[16]+=lw; break;
            case 17: accS[17]+=ls; accW[17]+=lw; break;
            default: accS[18]+=ls; accW[18]+=lw; break;
            }
        }
        __syncthreads();
    }

    // ---- cross-warp smem tree reduce (x tile dead; reuse buffer), then RED ----
    float* red = (float*)smemRaw;   // [KK][8][32] = 19456 B
    #pragma unroll
    for (int k=0;k<KK;k++) red[(k*8+warp)*32+lane] = accS[k];
    __syncthreads();
    for (int it=t; it<KK*32; it+=256){
        int k = it >> 5, ln = it & 31;
        float s = 0.f;
        #pragma unroll
        for (int w=0;w<8;w++) s += red[(k*8+w)*32+ln];
        atomicAdd(&g_Xs[(b*KK+k)*CC + c0 + ln], s);
    }
    __syncthreads();
    #pragma unroll
    for (int k=0;k<KK;k++) red[(k*8+warp)*32+lane] = accW[k];
    __syncthreads();
    for (int it=t; it<KK*32; it+=256){
        int k = it >> 5, ln = it & 31;
        float s = 0.f;
        #pragma unroll
        for (int w=0;w<8;w++) s += red[(k*8+w)*32+ln];
        atomicAdd(&g_Xw[(b*KK+k)*CC + c0 + ln], s);
    }
}

// ---------------- pass 4: tiny GEMMs -> g[k][d], S1[d][k] ----------------
__global__ void k_smallmm(const float* __restrict__ w1, const float* __restrict__ b1,
                          const float* __restrict__ w2, const float* __restrict__ b2){
    int b = blockIdx.x, t = threadIdx.x;   // t = output channel d (128 threads)
    __shared__ float sXw[KK][CC], sXs[KK][CC], sZ[KK], sCnt[KK];
    for (int i=t; i<KK*CC; i+=CC){
        sXw[i/CC][i%CC] = g_Xw[b*KK*CC + i];
        sXs[i/CC][i%CC] = g_Xs[b*KK*CC + i];
    }
    if (t < KK){
        sZ[t]   = fmaxf(g_Z[b*KK+t], 1e-30f);
        sCnt[t] = g_cnt[b*KK+t];
    }
    __syncthreads();
    float ga[KK], sa[KK];
    #pragma unroll
    for (int k=0;k<KK;k++){ ga[k]=0.f; sa[k]=0.f; }
    for (int c=0;c<CC;c++){
        float w2v = w2[t*CC + c];
        float w1v = w1[t*CC + c];
        #pragma unroll
        for (int k=0;k<KK;k++){
            ga[k] = fmaf(sXw[k][c], w2v, ga[k]);
            sa[k] = fmaf(sXs[k][c], w1v, sa[k]);
        }
    }
    #pragma unroll
    for (int k=0;k<KK;k++){
        g_gmat[(b*KK+k)*CC + t] = ga[k]/sZ[k] + b2[t];
        g_S1[(b*CC+t)*KK + k]   = sa[k] + b1[t]*sCnt[k];
    }
}

// ---------------- pass 5: gc = S1 @ g / sqrt(C), row softmax (128 thr) -------
__global__ void k_out(float* __restrict__ out){
    int b = blockIdx.y, d1 = blockIdx.x, t = threadIdx.x;
    __shared__ float s1[KK];
    __shared__ float redm[4], reds[4];
    if (t < KK) s1[t] = g_S1[(b*CC+d1)*KK + t];
    __syncthreads();
    float acc = 0.f;
    const float* gb = g_gmat + b*KK*CC + t;
    #pragma unroll
    for (int k=0;k<KK;k++) acc = fmaf(s1[k], gb[k*CC], acc);
    acc *= 0.08838834764831845f;
    float m = acc;
    #pragma unroll
    for (int o=16;o;o>>=1) m = fmaxf(m, __shfl_xor_sync(0xffffffffu, m, o));
    if ((t&31)==0) redm[t>>5] = m;
    __syncthreads();
    m = fmaxf(fmaxf(redm[0],redm[1]), fmaxf(redm[2],redm[3]));
    float e = expf(acc - m);
    float s = e;
    #pragma unroll
    for (int o=16;o;o>>=1) s += __shfl_xor_sync(0xffffffffu, s, o);
    if ((t&31)==0) reds[t>>5] = s;
    __syncthreads();
    s = reds[0]+reds[1]+reds[2]+reds[3];
    out[((size_t)(b*CC+d1))*CC + t] = e/s;
}

// ---------------- launch ----------------
extern "C" void kernel_launch(void* const* d_in, const int* in_sizes, int n_in,
                              void* d_out, int out_size){
    const float* x     = (const float*)d_in[0];
    const float* preds = (const float*)d_in[1];
    const float* w1    = (const float*)d_in[2];
    const float* b1    = (const float*)d_in[3];
    const float* w2    = (const float*)d_in[4];
    const float* b2    = (const float*)d_in[5];
    float* out = (float*)d_out;

    k_init<<<80,256>>>();
    k_argmax <<<dim3(NPIX/256, BB), 256>>>(preds);
    k_weights<<<dim3(NPIX/256, BB), 256>>>();
    k_segsum <<<dim3(NPIX/PTILE, CC/32, BB), 256>>>(x);
    k_smallmm<<<BB, CC>>>(w1, b1, w2, b2);
    k_out    <<<dim3(CC, BB), CC>>>(out);
    (void)in_sizes; (void)n_in; (void)out_size;
}

// round 5
// speedup vs baseline: 1.8426x; 1.4229x over previous
#include <cuda_runtime.h>

#define BB 8
#define CC 128
#define KK 19
#define NPIX 65536
#define BN (BB*NPIX)

// ---------------- scratch (device globals; no allocation) ----------------
__device__ float2 g_em[BN];          // sorted per 128-seg: (e, bits((i<<8)|cls))
__device__ float  g_Z[BB*KK];        // per-(b,k) sum of exp
__device__ float  g_cnt[BB*KK];      // per-(b,k) pixel count
__device__ float  g_Xs[BB*KK*CC];    // unweighted segment sums of x
__device__ float  g_Xw[BB*KK*CC];    // exp-weighted segment sums of x
__device__ float  g_gmat[BB*KK*CC];  // g[b][k][d]
__device__ float  g_S1[BB*CC*KK];    // S1[b][d][k]

// ---------------- pass 0: zero accumulators ----------------
__global__ void k_init(){
    int i = blockIdx.x*blockDim.x + threadIdx.x;
    int stride = gridDim.x*blockDim.x;
    if (i < BB*KK){ g_Z[i]=0.f; g_cnt[i]=0.f; }
    for (int j=i; j<BB*KK*CC; j+=stride){ g_Xs[j]=0.f; g_Xw[j]=0.f; }
}

// ---- pass 1 (fused): argmax + e=exp(p) + counting-sort per 128-seg + Z,cnt ----
// Softmax over segment is shift-invariant -> no per-class max pass needed.
// Block: 256 threads, 4 consecutive pixels each -> 1024 pixels = 8 segs.
// warp w owns seg w (pixels [w*128,(w+1)*128) of the block tile).
#define FPB 1024
__global__ void __launch_bounds__(256) k_pred(const float* __restrict__ preds){
    const int b  = blockIdx.y;
    const int p0 = blockIdx.x*FPB;
    const int t  = threadIdx.x;
    const int warp = t >> 5;

    const float4* r0 = (const float4*)(preds + (size_t)b*KK*NPIX + p0);
    float4 v = __ldg(&r0[t]);
    float bv[4] = {v.x, v.y, v.z, v.w};
    int   bk[4] = {0,0,0,0};
    #pragma unroll
    for (int k=1;k<KK;k++){
        float4 u = __ldg(&r0[t + k*(NPIX/4)]);
        if (u.x > bv[0]){ bv[0]=u.x; bk[0]=k; }
        if (u.y > bv[1]){ bv[1]=u.y; bk[1]=k; }
        if (u.z > bv[2]){ bv[2]=u.z; bk[2]=k; }
        if (u.w > bv[3]){ bv[3]=u.w; bk[3]=k; }
    }
    float ev[4];
    #pragma unroll
    for (int j=0;j<4;j++) ev[j] = expf(bv[j]);

    __shared__ int   segCnt[8][20];
    __shared__ int   segStart[8][20];
    __shared__ float sZ[KK];
    if (t < 8*20) segCnt[t/20][t%20] = 0;
    if (t < KK)   sZ[t] = 0.f;
    __syncthreads();

    int rk[4];
    #pragma unroll
    for (int j=0;j<4;j++){
        rk[j] = atomicAdd(&segCnt[warp][bk[j]], 1);
        atomicAdd(&sZ[bk[j]], ev[j]);
    }
    __syncthreads();
    if (t < 8){
        int s = 0;
        #pragma unroll
        for (int k=0;k<KK;k++){ segStart[t][k] = s; s += segCnt[t][k]; }
    }
    __syncthreads();

    const int segbase = b*NPIX + p0 + warp*128;
    const int i0 = 4*(t & 31);
    #pragma unroll
    for (int j=0;j<4;j++){
        int pos = segStart[warp][bk[j]] + rk[j];
        g_em[segbase + pos] = make_float2(ev[j], __int_as_float(((i0+j)<<8) | bk[j]));
    }
    if (t < KK){
        atomicAdd(&g_Z[b*KK+t], sZ[t]);
        int c = 0;
        #pragma unroll
        for (int w=0;w<8;w++) c += segCnt[w][t];
        atomicAdd(&g_cnt[b*KK+t], (float)c);
    }
}

// ---------------- pass 2: heavy segment sums over x ----------------
#define PTILE 1024
#define PCH   128
#define NCHUNK (PTILE/PCH)
#define XSTRIDE 130                       // 520 B/row: 8B aligned, 2-way conflict max
#define XWORDS (32*XSTRIDE)
#define OFF_EM   (2*XWORDS*4)             // 33280
#define SMEM_BYTES (OFF_EM + 2*PCH*8)     // 35328

__device__ __forceinline__ void cpasync8(unsigned saddr, const void* gaddr){
    asm volatile("cp.async.ca.shared.global [%0], [%1], 8;" :: "r"(saddr), "l"(gaddr));
}
__device__ __forceinline__ void cpcommit(){ asm volatile("cp.async.commit_group;"); }
template<int N> __device__ __forceinline__ void cpwait(){ asm volatile("cp.async.wait_group %0;" :: "n"(N)); }

__global__ void __launch_bounds__(256, 4) k_segsum(const float* __restrict__ x){
    __shared__ __align__(16) unsigned char smemRaw[SMEM_BYTES];
    float*  sXf  = (float*)smemRaw;
    float2* sEM  = (float2*)(smemRaw + OFF_EM);

    const int b    = blockIdx.z;
    const int c0   = blockIdx.y*32;
    const int pix0 = blockIdx.x*PTILE;
    const int t    = threadIdx.x;
    const int warp = t >> 5;
    const int lane = t & 31;

    const float* xb = x + (size_t)b*CC*NPIX + (size_t)c0*NPIX + pix0;
    unsigned sbase = (unsigned)__cvta_generic_to_shared(smemRaw);

    auto prefetch = [&](int ch, int buf){
        const float* gsrc = xb + ch*PCH;
        unsigned sx = sbase + (unsigned)buf*(XWORDS*4);
        #pragma unroll
        for (int j=0;j<8;j++){
            int u    = t + j*256;
            int row  = u >> 6;
            int unit = u & 63;
            cpasync8(sx + (unsigned)(row*XSTRIDE + unit*2)*4,
                     gsrc + (size_t)row*NPIX + unit*2);
        }
        if (t < 128){   // em: 128 float2 = 128 x 8B
            cpasync8(sbase + OFF_EM + (unsigned)buf*(PCH*8) + (unsigned)t*8,
                     g_em + (size_t)b*NPIX + pix0 + ch*PCH + t);
        }
        cpcommit();
    };

    float accS[KK], accW[KK];
    #pragma unroll
    for (int k=0;k<KK;k++){ accS[k]=0.f; accW[k]=0.f; }

    prefetch(0, 0);
    for (int ch=0; ch<NCHUNK; ++ch){
        int buf = ch & 1;
        if (ch+1 < NCHUNK) prefetch(ch+1, buf^1);
        if (ch+1 < NCHUNK) cpwait<1>(); else cpwait<0>();
        __syncthreads();

        const float*  xrow  = &sXf[buf*XWORDS + lane*XSTRIDE];
        const float2* emArr = &sEM[buf*PCH];

        const int wp0  = warp*16;
        const int wend = wp0 + 16;
        int p = wp0;
        float2 em = emArr[p];
        while (p < wend){
            int k = __float_as_int(em.y) & 255;
            float ls = 0.f, lw = 0.f;
            bool cont = true;
            while (cont){
                float v = xrow[__float_as_int(em.y) >> 8];
                ls += v;
                lw = fmaf(v, em.x, lw);
                ++p;
                if (p < wend){
                    em = emArr[p];
                    cont = ((__float_as_int(em.y) & 255) == k);
                } else cont = false;
            }
            switch(k){
            case 0:  accS[0] +=ls; accW[0] +=lw; break;
            case 1:  accS[1] +=ls; accW[1] +=lw; break;
            case 2:  accS[2] +=ls; accW[2] +=lw; break;
            case 3:  accS[3] +=ls; accW[3] +=lw; break;
            case 4:  accS[4] +=ls; accW[4] +=lw; break;
            case 5:  accS[5] +=ls; accW[5] +=lw; break;
            case 6:  accS[6] +=ls; accW[6] +=lw; break;
            case 7:  accS[7] +=ls; accW[7] +=lw; break;
            case 8:  accS[8] +=ls; accW[8] +=lw; break;
            case 9:  accS[9] +=ls; accW[9] +=lw; break;
            case 10: accS[10]+=ls; accW[10]+=lw; break;
            case 11: accS[11]+=ls; accW[11]+=lw; break;
            case 12: accS[12]+=ls; accW[12]+=lw; break;
            case 13: accS[13]+=ls; accW[13]+=lw; break;
            case 14: accS[14]+=ls; accW[14]+=lw; break;
            case 15: accS[15]+=ls; accW[15]+=lw; break;
            case 16: accS[16]+=ls; accW[16]+=lw; break;
            case 17: accS[17]+=ls; accW[17]+=lw; break;
            default: accS[18]+=ls; accW[18]+=lw; break;
            }
        }
        __syncthreads();
    }

    // ---- cross-warp smem tree reduce (x tile dead; reuse), then global RED ----
    float* red = (float*)smemRaw;   // [KK][8][32]
    #pragma unroll
    for (int k=0;k<KK;k++) red[(k*8+warp)*32+lane] = accS[k];
    __syncthreads();
    for (int it=t; it<KK*32; it+=256){
        int k = it >> 5, ln = it & 31;
        float s = 0.f;
        #pragma unroll
        for (int w=0;w<8;w++) s += red[(k*8+w)*32+ln];
        atomicAdd(&g_Xs[(b*KK+k)*CC + c0 + ln], s);
    }
    __syncthreads();
    #pragma unroll
    for (int k=0;k<KK;k++) red[(k*8+warp)*32+lane] = accW[k];
    __syncthreads();
    for (int it=t; it<KK*32; it+=256){
        int k = it >> 5, ln = it & 31;
        float s = 0.f;
        #pragma unroll
        for (int w=0;w<8;w++) s += red[(k*8+w)*32+ln];
        atomicAdd(&g_Xw[(b*KK+k)*CC + c0 + ln], s);
    }
}

// ---------------- pass 3: tiny GEMMs, one block per (k,b) ----------------
__global__ void __launch_bounds__(128) k_smallmm(
        const float* __restrict__ w1, const float* __restrict__ b1,
        const float* __restrict__ w2, const float* __restrict__ b2){
    const int k = blockIdx.x, b = blockIdx.y, t = threadIdx.x;  // 128 threads
    __shared__ float sxs[CC], sxw[CC];
    __shared__ float sW1[CC][33], sW2[CC][33];
    sxs[t] = g_Xs[(b*KK+k)*CC + t];
    sxw[t] = g_Xw[(b*KK+k)*CC + t];
    __syncthreads();

    float ga = 0.f, sa = 0.f;
    const int cc0 = t & 31, d0 = t >> 5;
    for (int c0=0; c0<CC; c0+=32){
        #pragma unroll
        for (int j=0;j<32;j++){
            int d = j*4 + d0;
            sW1[d][cc0] = w1[d*CC + c0 + cc0];
            sW2[d][cc0] = w2[d*CC + c0 + cc0];
        }
        __syncthreads();
        #pragma unroll
        for (int cc=0;cc<32;cc++){
            ga = fmaf(sxw[c0+cc], sW2[t][cc], ga);
            sa = fmaf(sxs[c0+cc], sW1[t][cc], sa);
        }
        __syncthreads();
    }
    float Z   = fmaxf(g_Z[b*KK+k], 1e-30f);
    float cnt = g_cnt[b*KK+k];
    g_gmat[(b*KK+k)*CC + t] = ga/Z + b2[t];
    g_S1[(b*CC+t)*KK + k]   = sa + b1[t]*cnt;
}

// ---------------- pass 4: gc = S1 @ g / sqrt(C), row softmax ----------------
__global__ void __launch_bounds__(128) k_out(float* __restrict__ out){
    int b = blockIdx.y, d1 = blockIdx.x, t = threadIdx.x;
    __shared__ float s1[KK];
    __shared__ float redm[4], reds[4];
    if (t < KK) s1[t] = g_S1[(b*CC+d1)*KK + t];
    __syncthreads();
    float acc = 0.f;
    const float* gb = g_gmat + b*KK*CC + t;
    #pragma unroll
    for (int k=0;k<KK;k++) acc = fmaf(s1[k], gb[k*CC], acc);
    acc *= 0.08838834764831845f;
    float m = acc;
    #pragma unroll
    for (int o=16;o;o>>=1) m = fmaxf(m, __shfl_xor_sync(0xffffffffu, m, o));
    if ((t&31)==0) redm[t>>5] = m;
    __syncthreads();
    m = fmaxf(fmaxf(redm[0],redm[1]), fmaxf(redm[2],redm[3]));
    float e = expf(acc - m);
    float s = e;
    #pragma unroll
    for (int o=16;o;o>>=1) s += __shfl_xor_sync(0xffffffffu, s, o);
    if ((t&31)==0) reds[t>>5] = s;
    __syncthreads();
    s = reds[0]+reds[1]+reds[2]+reds[3];
    out[((size_t)(b*CC+d1))*CC + t] = e/s;
}

// ---------------- launch ----------------
extern "C" void kernel_launch(void* const* d_in, const int* in_sizes, int n_in,
                              void* d_out, int out_size){
    const float* x     = (const float*)d_in[0];
    const float* preds = (const float*)d_in[1];
    const float* w1    = (const float*)d_in[2];
    const float* b1    = (const float*)d_in[3];
    const float* w2    = (const float*)d_in[4];
    const float* b2    = (const float*)d_in[5];
    float* out = (float*)d_out;

    k_init   <<<80,256>>>();
    k_pred   <<<dim3(NPIX/FPB, BB), 256>>>(preds);
    k_segsum <<<dim3(NPIX/PTILE, CC/32, BB), 256>>>(x);
    k_smallmm<<<dim3(KK, BB), 128>>>(w1, b1, w2, b2);
    k_out    <<<dim3(CC, BB), CC>>>(out);
    (void)in_sizes; (void)n_in; (void)out_size;
}